// round 1
// baseline (speedup 1.0000x reference)
#include <cuda_runtime.h>
#include <cuda_bf16.h>

#define N_  50000
#define E_  1600000
#define H_  128
#define NU_ 49232
#define NM_ 512
#define NS_ 256

// ---------------- scratch (no allocations allowed) ----------------
__device__ float g_h[N_ * H_];      // transformed features of current layer
__device__ float g_out[N_ * H_];    // aggregated output / next layer input
__device__ float g_el[N_];
__device__ float g_er[N_];
__device__ int   g_deg[N_];
__device__ int   g_ptr[N_ + 1];
__device__ int   g_cur[N_];
__device__ int   g_csr_src[E_];     // src node id per CSR slot (grouped by dst)
__device__ float g_T[NM_ * H_];     // model_emb @ Wb

// ---------------- CSR build ----------------
__global__ void k_zero_deg() {
    int i = blockIdx.x * blockDim.x + threadIdx.x;
    if (i < N_) g_deg[i] = 0;
}

__global__ void k_hist(const int* __restrict__ dstI) {
    int i = blockIdx.x * blockDim.x + threadIdx.x;
    if (i < E_) atomicAdd(&g_deg[dstI[i]], 1);
}

// single-block exclusive scan over 50000 degrees
__global__ void k_scan() {
    __shared__ int ssum[1024];
    const int tid = threadIdx.x;
    const int chunk = (N_ + 1023) / 1024;   // 49
    const int start = tid * chunk;
    int s = 0;
    for (int i = 0; i < chunk; i++) {
        int idx = start + i;
        if (idx < N_) s += g_deg[idx];
    }
    ssum[tid] = s;
    __syncthreads();
    for (int off = 1; off < 1024; off <<= 1) {
        int v = 0;
        if (tid >= off) v = ssum[tid - off];
        __syncthreads();
        ssum[tid] += v;
        __syncthreads();
    }
    int run = (tid > 0) ? ssum[tid - 1] : 0;   // exclusive base for this chunk
    for (int i = 0; i < chunk; i++) {
        int idx = start + i;
        if (idx < N_) {
            g_ptr[idx] = run;
            g_cur[idx] = run;
            run += g_deg[idx];
        }
    }
    if (tid == 1023) g_ptr[N_] = ssum[1023];
}

__global__ void k_scatter(const int* __restrict__ srcI, const int* __restrict__ dstI) {
    int i = blockIdx.x * blockDim.x + threadIdx.x;
    if (i < E_) {
        int p = atomicAdd(&g_cur[dstI[i]], 1);
        g_csr_src[p] = srcI[i];
    }
}

// ---------------- h = X @ W  (50000x128 @ 128x128) ----------------
// block: 256 threads, 32 rows x 128 cols. xs tile in smem, W streamed via L1.
__global__ __launch_bounds__(256) void k_gemm(const float* __restrict__ Xext,
                                              int use_ext,
                                              const float* __restrict__ W) {
    __shared__ float xs[32][129];
    const float* __restrict__ X = use_ext ? Xext : g_out;
    const int row0 = blockIdx.x * 32;
    const int tid = threadIdx.x;
    const int c = tid & 127;
    const int rbase = (tid >> 7) * 16;   // 0 or 16

    for (int i = tid; i < 32 * 128; i += 256) {
        int r = i >> 7, k = i & 127;
        int gr = row0 + r;
        xs[r][k] = (gr < N_) ? X[gr * H_ + k] : 0.f;
    }
    __syncthreads();

    float acc[16];
#pragma unroll
    for (int r = 0; r < 16; r++) acc[r] = 0.f;

    for (int k = 0; k < 128; k++) {
        float w = __ldg(&W[k * H_ + c]);
#pragma unroll
        for (int r = 0; r < 16; r++)
            acc[r] += xs[rbase + r][k] * w;
    }

#pragma unroll
    for (int r = 0; r < 16; r++) {
        int gr = row0 + rbase + r;
        if (gr < N_) g_h[gr * H_ + c] = acc[r];
    }
}

// ---------------- el = h@al, er = h@ar (one warp per row) ----------------
__device__ __forceinline__ float warpSum(float v) {
#pragma unroll
    for (int o = 16; o; o >>= 1) v += __shfl_xor_sync(0xffffffffu, v, o);
    return v;
}
__device__ __forceinline__ float warpMax(float v) {
#pragma unroll
    for (int o = 16; o; o >>= 1) v = fmaxf(v, __shfl_xor_sync(0xffffffffu, v, o));
    return v;
}

__global__ __launch_bounds__(256) void k_dots(const float* __restrict__ al,
                                              const float* __restrict__ ar) {
    int warp = (blockIdx.x * blockDim.x + threadIdx.x) >> 5;
    int lane = threadIdx.x & 31;
    if (warp >= N_) return;
    float4 h = *(const float4*)(&g_h[warp * H_ + lane * 4]);
    float4 A = *(const float4*)(&al[lane * 4]);
    float4 R = *(const float4*)(&ar[lane * 4]);
    float a = h.x * A.x + h.y * A.y + h.z * A.z + h.w * A.w;
    float b = h.x * R.x + h.y * R.y + h.z * R.z + h.w * R.w;
    a = warpSum(a);
    b = warpSum(b);
    if (lane == 0) {
        g_el[warp] = a;
        g_er[warp] = b;
    }
}

// ---------------- fused edge-softmax + aggregation (one warp per dst) -----
// out[dst] = (sum_e exp(e-m) * h[src_e]) / (sum_e exp(e-m) + 1e-10) + b
__global__ __launch_bounds__(256) void k_agg(const float* __restrict__ bvec,
                                             int do_relu) {
    const int lane = threadIdx.x & 31;
    const int node = blockIdx.x * 8 + (threadIdx.x >> 5);
    if (node >= N_) return;

    const int beg = g_ptr[node];
    const int end = g_ptr[node + 1];
    const float eld = g_el[node];

    // pass 1: max of leaky_relu(el[dst]+er[src])
    float mx = -1e30f;
    for (int i = beg + lane; i < end; i += 32) {
        int s = g_csr_src[i];
        float t = eld + g_er[s];
        mx = fmaxf(mx, fmaxf(t, 0.2f * t));
    }
    mx = warpMax(mx);

    // pass 2: unnormalized accumulate + denominator
    float4 acc = make_float4(0.f, 0.f, 0.f, 0.f);
    float psum = 0.f;
    for (int base = beg; base < end; base += 32) {
        int i = base + lane;
        int s = 0;
        float w = 0.f;
        if (i < end) {
            s = g_csr_src[i];
            float t = eld + g_er[s];
            t = fmaxf(t, 0.2f * t);
            w = __expf(t - mx);
            psum += w;
        }
        int cnt = min(32, end - base);
        for (int t = 0; t < cnt; t++) {
            int ss = __shfl_sync(0xffffffffu, s, t);
            float ww = __shfl_sync(0xffffffffu, w, t);
            float4 hv = *(const float4*)(&g_h[ss * H_ + lane * 4]);
            acc.x += ww * hv.x;
            acc.y += ww * hv.y;
            acc.z += ww * hv.z;
            acc.w += ww * hv.w;
        }
    }
    float ssum = warpSum(psum);
    float inv = 1.f / (ssum + 1e-10f);

    float4 bq = *(const float4*)(&bvec[lane * 4]);
    float4 o;
    o.x = acc.x * inv + bq.x;
    o.y = acc.y * inv + bq.y;
    o.z = acc.z * inv + bq.z;
    o.w = acc.w * inv + bq.w;
    if (do_relu) {
        o.x = fmaxf(o.x, 0.f);
        o.y = fmaxf(o.y, 0.f);
        o.z = fmaxf(o.z, 0.f);
        o.w = fmaxf(o.w, 0.f);
    }
    *(float4*)(&g_out[node * H_ + lane * 4]) = o;
}

// ---------------- bilinear head ----------------
// T[m] = model_emb[m] @ Wb        (512 x 128)
__global__ __launch_bounds__(128) void k_bil1(const float* __restrict__ Wb) {
    __shared__ float row[128];
    const int m = blockIdx.x;
    const int c = threadIdx.x;
    row[c] = g_out[(NU_ + m) * H_ + c];
    __syncthreads();
    float a = 0.f;
#pragma unroll 8
    for (int k = 0; k < 128; k++)
        a += row[k] * __ldg(&Wb[k * H_ + c]);
    g_T[m * H_ + c] = a;
}

// scores[m][s] = T[m] . server_emb[s] + bb
__global__ __launch_bounds__(256) void k_bil2(const float* __restrict__ bb,
                                              float* __restrict__ out) {
    __shared__ float row[128];
    const int m = blockIdx.x;
    const int s = threadIdx.x;
    if (s < 128) row[s] = g_T[m * H_ + s];
    __syncthreads();
    const float4* sv = (const float4*)(&g_out[(NU_ + NM_ + s) * H_]);
    float a = 0.f;
#pragma unroll 8
    for (int k = 0; k < 32; k++) {
        float4 v = __ldg(&sv[k]);
        a += row[4 * k + 0] * v.x + row[4 * k + 1] * v.y +
             row[4 * k + 2] * v.z + row[4 * k + 3] * v.w;
    }
    out[m * NS_ + s] = a + bb[0];
}

// ---------------- launch ----------------
extern "C" void kernel_launch(void* const* d_in, const int* in_sizes, int n_in,
                              void* d_out, int out_size) {
    (void)in_sizes; (void)n_in; (void)out_size;
    const float* x   = (const float*)d_in[0];
    const int*   ei  = (const int*)d_in[1];
    const float* W1  = (const float*)d_in[2];
    const float* al1 = (const float*)d_in[3];
    const float* ar1 = (const float*)d_in[4];
    const float* b1  = (const float*)d_in[5];
    const float* W2  = (const float*)d_in[6];
    const float* al2 = (const float*)d_in[7];
    const float* ar2 = (const float*)d_in[8];
    const float* b2  = (const float*)d_in[9];
    const float* W3  = (const float*)d_in[10];
    const float* al3 = (const float*)d_in[11];
    const float* ar3 = (const float*)d_in[12];
    const float* b3  = (const float*)d_in[13];
    const float* Wb  = (const float*)d_in[14];
    const float* bb  = (const float*)d_in[15];
    float* out = (float*)d_out;

    const int* srcI = ei;
    const int* dstI = ei + E_;

    const int EB = (E_ + 255) / 256;          // 6250
    const int NB8 = (N_ + 7) / 8;             // 6250 (warp per node, 8 warps/block)
    const int GB = (N_ + 31) / 32;            // 1563 gemm blocks

    // CSR build (edge_index is the same every call; rebuilt deterministically-enough)
    k_zero_deg<<<(N_ + 255) / 256, 256>>>();
    k_hist<<<EB, 256>>>(dstI);
    k_scan<<<1, 1024>>>();
    k_scatter<<<EB, 256>>>(srcI, dstI);

    // layer 1
    k_gemm<<<GB, 256>>>(x, 1, W1);
    k_dots<<<NB8, 256>>>(al1, ar1);
    k_agg<<<NB8, 256>>>(b1, 1);
    // layer 2
    k_gemm<<<GB, 256>>>(nullptr, 0, W2);
    k_dots<<<NB8, 256>>>(al2, ar2);
    k_agg<<<NB8, 256>>>(b2, 1);
    // layer 3
    k_gemm<<<GB, 256>>>(nullptr, 0, W3);
    k_dots<<<NB8, 256>>>(al3, ar3);
    k_agg<<<NB8, 256>>>(b3, 0);

    // bilinear head
    k_bil1<<<NM_, 128>>>(Wb);
    k_bil2<<<NM_, 256>>>(bb, out);
}

// round 4
// speedup vs baseline: 1.5082x; 1.5082x over previous
#include <cuda_runtime.h>
#include <cuda_fp16.h>
#include <cuda_bf16.h>

#define N_  50000
#define E_  1600000
#define H_  128
#define NU_ 49232
#define NM_ 512
#define NS_ 256
#define NOUT_ (NM_ + NS_)   // 768

// ---------------- scratch (no allocations allowed) ----------------
__device__ float  g_h[N_ * H_];      // fp32 h (layer 3 only)
__device__ __half g_hh[N_ * H_];     // fp16 h (layers 1-2)
__device__ float  g_out[N_ * H_];    // aggregated output / next layer input
__device__ float  g_el[N_];
__device__ float  g_er[N_];
__device__ int    g_deg[N_];
__device__ int    g_ptr[N_ + 1];
__device__ int    g_cur[N_];
__device__ int    g_csr[E_];         // src node id per CSR slot (grouped by dst)
__device__ int    g_mark[N_];
__device__ int    g_list2[N_];       // frontier for layer-2 outputs / layer-3 gemm
__device__ int    g_cnt2;
__device__ float  g_T[NM_ * H_];     // model_emb @ Wb

// ---------------- init ----------------
__global__ void k_init() {
    int i = blockIdx.x * blockDim.x + threadIdx.x;
    if (i < N_) { g_deg[i] = 0; g_mark[i] = 0; }
    if (i == 0) g_cnt2 = 0;
}

// ---------------- CSR build ----------------
__global__ void k_hist(const int* __restrict__ dstI) {
    int i = blockIdx.x * blockDim.x + threadIdx.x;   // quads
    if (i < E_ / 4) {
        int4 d = ((const int4*)dstI)[i];
        atomicAdd(&g_deg[d.x], 1);
        atomicAdd(&g_deg[d.y], 1);
        atomicAdd(&g_deg[d.z], 1);
        atomicAdd(&g_deg[d.w], 1);
    }
}

// single-block exclusive scan over 50000 degrees
__global__ void k_scan() {
    __shared__ int ssum[1024];
    const int tid = threadIdx.x;
    const int chunk = (N_ + 1023) / 1024;   // 49
    const int start = tid * chunk;
    int s = 0;
    for (int i = 0; i < chunk; i++) {
        int idx = start + i;
        if (idx < N_) s += g_deg[idx];
    }
    ssum[tid] = s;
    __syncthreads();
    for (int off = 1; off < 1024; off <<= 1) {
        int v = 0;
        if (tid >= off) v = ssum[tid - off];
        __syncthreads();
        ssum[tid] += v;
        __syncthreads();
    }
    int run = (tid > 0) ? ssum[tid - 1] : 0;
    for (int i = 0; i < chunk; i++) {
        int idx = start + i;
        if (idx < N_) {
            g_ptr[idx] = run;
            g_cur[idx] = run;
            run += g_deg[idx];
        }
    }
    if (tid == 1023) g_ptr[N_] = ssum[1023];
}

__global__ void k_scatter(const int* __restrict__ srcI, const int* __restrict__ dstI) {
    int i = blockIdx.x * blockDim.x + threadIdx.x;   // quads
    if (i < E_ / 4) {
        int4 s = ((const int4*)srcI)[i];
        int4 d = ((const int4*)dstI)[i];
        g_csr[atomicAdd(&g_cur[d.x], 1)] = s.x;
        g_csr[atomicAdd(&g_cur[d.y], 1)] = s.y;
        g_csr[atomicAdd(&g_cur[d.z], 1)] = s.z;
        g_csr[atomicAdd(&g_cur[d.w], 1)] = s.w;
    }
}

// ---------------- frontier for layer-2 outputs ----------------
__global__ void k_mark() {             // one warp per output node
    int w = blockIdx.x * 8 + (threadIdx.x >> 5);
    int lane = threadIdx.x & 31;
    if (w >= NOUT_) return;
    int node = NU_ + w;
    if (lane == 0) g_mark[node] = 1;
    int beg = g_ptr[node], end = g_ptr[node + 1];
    for (int i = beg + lane; i < end; i += 32) g_mark[g_csr[i]] = 1;
}

__global__ void k_compact() {
    int i = blockIdx.x * blockDim.x + threadIdx.x;
    if (i < N_ && g_mark[i]) {
        int p = atomicAdd(&g_cnt2, 1);
        g_list2[p] = i;
    }
}

// ---------------- warp helpers ----------------
__device__ __forceinline__ float warpSum(float v) {
#pragma unroll
    for (int o = 16; o; o >>= 1) v += __shfl_xor_sync(0xffffffffu, v, o);
    return v;
}
__device__ __forceinline__ float warpMax(float v) {
#pragma unroll
    for (int o = 16; o; o >>= 1) v = fmaxf(v, __shfl_xor_sync(0xffffffffu, v, o));
    return v;
}

// ---------------- fused h = X @ W + (el, er) epilogue ----------------
// 64-row tile, 256 threads, each thread: 8 rows x 4 cols.
template <int WRITE_HALF>
__global__ __launch_bounds__(256) void k_gemm(
    const float* __restrict__ Xext, int use_ext,
    int use_list, int nrows_fixed,
    const float* __restrict__ W,
    const float* __restrict__ al, const float* __restrict__ ar)
{
    __shared__ float xs[64][132];
    __shared__ int rid[64];

    const int nrows = use_list ? g_cnt2 : nrows_fixed;
    const int row0 = blockIdx.x * 64;
    if (row0 >= nrows) return;
    const float* __restrict__ X = use_ext ? Xext : g_out;
    const int tid = threadIdx.x;

    for (int r = tid; r < 64; r += 256) {
        int rr = row0 + r;
        rid[r] = (rr < nrows) ? (use_list ? g_list2[rr] : rr) : -1;
    }
    __syncthreads();

#pragma unroll
    for (int it = 0; it < 8; it++) {
        int idx = tid + it * 256;        // 0..2047 (64 rows x 32 quads)
        int r = idx >> 5;
        int q = idx & 31;
        int node = rid[r];
        float4 v = make_float4(0.f, 0.f, 0.f, 0.f);
        if (node >= 0) v = ((const float4*)(X + (size_t)node * H_))[q];
        *(float4*)&xs[r][q * 4] = v;
    }
    __syncthreads();

    const int lane = tid & 31;
    const int cq = lane * 4;             // column quad base
    const int r8 = (tid >> 5) * 8;       // row group base

    float acc[8][4];
#pragma unroll
    for (int r = 0; r < 8; r++)
#pragma unroll
        for (int j = 0; j < 4; j++) acc[r][j] = 0.f;

    for (int k = 0; k < 128; k += 4) {
        float4 w0 = __ldg((const float4*)&W[(k + 0) * H_ + cq]);
        float4 w1 = __ldg((const float4*)&W[(k + 1) * H_ + cq]);
        float4 w2 = __ldg((const float4*)&W[(k + 2) * H_ + cq]);
        float4 w3 = __ldg((const float4*)&W[(k + 3) * H_ + cq]);
#pragma unroll
        for (int r = 0; r < 8; r++) {
            float4 xv = *(const float4*)&xs[r8 + r][k];
            acc[r][0] += xv.x * w0.x + xv.y * w1.x + xv.z * w2.x + xv.w * w3.x;
            acc[r][1] += xv.x * w0.y + xv.y * w1.y + xv.z * w2.y + xv.w * w3.y;
            acc[r][2] += xv.x * w0.z + xv.y * w1.z + xv.z * w2.z + xv.w * w3.z;
            acc[r][3] += xv.x * w0.w + xv.y * w1.w + xv.z * w2.w + xv.w * w3.w;
        }
    }

    // write h
#pragma unroll
    for (int r = 0; r < 8; r++) {
        int node = rid[r8 + r];
        if (node < 0) continue;
        if (WRITE_HALF) {
            __half2 h01 = __floats2half2_rn(acc[r][0], acc[r][1]);
            __half2 h23 = __floats2half2_rn(acc[r][2], acc[r][3]);
            uint2 pk;
            *reinterpret_cast<__half2*>(&pk.x) = h01;
            *reinterpret_cast<__half2*>(&pk.y) = h23;
            *reinterpret_cast<uint2*>(&g_hh[(size_t)node * H_ + cq]) = pk;
        } else {
            *(float4*)&g_h[(size_t)node * H_ + cq] =
                make_float4(acc[r][0], acc[r][1], acc[r][2], acc[r][3]);
        }
    }

    // el/er epilogue: warp spans all 128 cols for its 8 rows
    float4 alv = __ldg((const float4*)&al[cq]);
    float4 arv = __ldg((const float4*)&ar[cq]);
#pragma unroll
    for (int r = 0; r < 8; r++) {
        float p = acc[r][0] * alv.x + acc[r][1] * alv.y + acc[r][2] * alv.z + acc[r][3] * alv.w;
        float q = acc[r][0] * arv.x + acc[r][1] * arv.y + acc[r][2] * arv.z + acc[r][3] * arv.w;
        p = warpSum(p);
        q = warpSum(q);
        int node = rid[r8 + r];
        if (lane == 0 && node >= 0) { g_el[node] = p; g_er[node] = q; }
    }
}

// ---------------- fused edge-softmax + aggregation (online softmax) ------
template <int USE_HALF>
__global__ __launch_bounds__(256) void k_agg(
    int use_list, int node_off, int nfixed,
    const float* __restrict__ bvec, int do_relu)
{
    const int lane = threadIdx.x & 31;
    const int idx = blockIdx.x * 8 + (threadIdx.x >> 5);
    const int ncount = use_list ? g_cnt2 : nfixed;
    if (idx >= ncount) return;
    const int node = use_list ? g_list2[idx] : (node_off + idx);

    const int beg = g_ptr[node];
    const int end = g_ptr[node + 1];
    const float eld = g_el[node];

    float m = -1e30f, psum = 0.f;
    float4 acc = make_float4(0.f, 0.f, 0.f, 0.f);

    for (int base = beg; base < end; base += 32) {
        int i = base + lane;
        int s = 0;
        float t = -1e30f;
        if (i < end) {
            s = g_csr[i];
            float u = eld + g_er[s];
            t = fmaxf(u, 0.2f * u);          // leaky_relu(u, 0.2)
        }
        float cm = warpMax(t);
        float newm = fmaxf(m, cm);
        float sc = __expf(m - newm);
        psum *= sc;
        acc.x *= sc; acc.y *= sc; acc.z *= sc; acc.w *= sc;
        m = newm;
        float w = (i < end) ? __expf(t - m) : 0.f;
        psum += w;

        int cnt = min(32, end - base);
        for (int e = 0; e < cnt; e++) {
            int   ss = __shfl_sync(0xffffffffu, s, e);
            float ww = __shfl_sync(0xffffffffu, w, e);
            if (USE_HALF) {
                uint2 pk = *(const uint2*)&g_hh[(size_t)ss * H_ + lane * 4];
                float2 a = __half22float2(*reinterpret_cast<__half2*>(&pk.x));
                float2 b = __half22float2(*reinterpret_cast<__half2*>(&pk.y));
                acc.x += ww * a.x; acc.y += ww * a.y;
                acc.z += ww * b.x; acc.w += ww * b.y;
            } else {
                float4 hv = *(const float4*)&g_h[(size_t)ss * H_ + lane * 4];
                acc.x += ww * hv.x; acc.y += ww * hv.y;
                acc.z += ww * hv.z; acc.w += ww * hv.w;
            }
        }
    }

    float ssum = warpSum(psum);
    float inv = 1.f / (ssum + 1e-10f);

    float4 bq = *(const float4*)&bvec[lane * 4];
    float4 o;
    o.x = acc.x * inv + bq.x;
    o.y = acc.y * inv + bq.y;
    o.z = acc.z * inv + bq.z;
    o.w = acc.w * inv + bq.w;
    if (do_relu) {
        o.x = fmaxf(o.x, 0.f); o.y = fmaxf(o.y, 0.f);
        o.z = fmaxf(o.z, 0.f); o.w = fmaxf(o.w, 0.f);
    }
    *(float4*)&g_out[(size_t)node * H_ + lane * 4] = o;
}

// ---------------- bilinear head ----------------
__global__ __launch_bounds__(128) void k_bil1(const float* __restrict__ Wb) {
    __shared__ float row[128];
    const int m = blockIdx.x;
    const int c = threadIdx.x;
    row[c] = g_out[(size_t)(NU_ + m) * H_ + c];
    __syncthreads();
    float a = 0.f;
#pragma unroll 8
    for (int k = 0; k < 128; k++)
        a += row[k] * __ldg(&Wb[k * H_ + c]);
    g_T[m * H_ + c] = a;
}

__global__ __launch_bounds__(256) void k_bil2(const float* __restrict__ bb,
                                              float* __restrict__ out) {
    __shared__ float row[128];
    const int m = blockIdx.x;
    const int s = threadIdx.x;
    if (s < 128) row[s] = g_T[m * H_ + s];
    __syncthreads();
    const float4* sv = (const float4*)&g_out[(size_t)(NU_ + NM_ + s) * H_];
    float a = 0.f;
#pragma unroll 8
    for (int k = 0; k < 32; k++) {
        float4 v = __ldg(&sv[k]);
        a += row[4 * k + 0] * v.x + row[4 * k + 1] * v.y +
             row[4 * k + 2] * v.z + row[4 * k + 3] * v.w;
    }
    out[m * NS_ + s] = a + bb[0];
}

// ---------------- launch ----------------
extern "C" void kernel_launch(void* const* d_in, const int* in_sizes, int n_in,
                              void* d_out, int out_size) {
    (void)in_sizes; (void)n_in; (void)out_size;
    const float* x   = (const float*)d_in[0];
    const int*   ei  = (const int*)d_in[1];
    const float* W1  = (const float*)d_in[2];
    const float* al1 = (const float*)d_in[3];
    const float* ar1 = (const float*)d_in[4];
    const float* b1  = (const float*)d_in[5];
    const float* W2  = (const float*)d_in[6];
    const float* al2 = (const float*)d_in[7];
    const float* ar2 = (const float*)d_in[8];
    const float* b2  = (const float*)d_in[9];
    const float* W3  = (const float*)d_in[10];
    const float* al3 = (const float*)d_in[11];
    const float* ar3 = (const float*)d_in[12];
    const float* b3  = (const float*)d_in[13];
    const float* Wb  = (const float*)d_in[14];
    const float* bb  = (const float*)d_in[15];
    float* out = (float*)d_out;

    const int* srcI = ei;
    const int* dstI = ei + E_;

    const int EQ = ((E_ / 4) + 255) / 256;    // 1563: quad-vectorized edge blocks
    const int NB8 = (N_ + 7) / 8;             // 6250: warp-per-node blocks
    const int GB = (N_ + 63) / 64;            // 782: gemm blocks

    // CSR build + frontier
    k_init<<<(N_ + 255) / 256, 256>>>();
    k_hist<<<EQ, 256>>>(dstI);
    k_scan<<<1, 1024>>>();
    k_scatter<<<EQ, 256>>>(srcI, dstI);
    k_mark<<<(NOUT_ + 7) / 8, 256>>>();
    k_compact<<<(N_ + 255) / 256, 256>>>();

    // layer 1 (full graph, fp16 h)
    k_gemm<1><<<GB, 256>>>(x, 1, 0, N_, W1, al1, ar1);
    k_agg<1><<<NB8, 256>>>(0, 0, N_, b1, 1);
    // layer 2 (full gemm, aggregation restricted to frontier, fp16 h)
    k_gemm<1><<<GB, 256>>>(nullptr, 0, 0, N_, W2, al2, ar2);
    k_agg<1><<<NB8, 256>>>(1, 0, 0, b2, 1);
    // layer 3 (gemm restricted to frontier, aggregation only for 768 outputs, fp32)
    k_gemm<0><<<GB, 256>>>(nullptr, 0, 1, 0, W3, al3, ar3);
    k_agg<0><<<(NOUT_ + 7) / 8, 256>>>(0, NU_, NOUT_, b3, 0);

    // bilinear head
    k_bil1<<<NM_, 128>>>(Wb);
    k_bil2<<<NM_, 256>>>(bb, out);
}